// round 13
// baseline (speedup 1.0000x reference)
#include <cuda_runtime.h>
#include <cstdint>
#include <math.h>

// Problem sizes
#define NN   8192
#define MM   4096
#define FIN  256
#define DD   128
#define CAPN 64
#define CAPE 128

// ---------------- device scratch ----------------
__device__ __align__(16) float g_v1[FIN];
__device__ __align__(16) float g_v2[FIN];
__device__ __align__(16) float g_w3v[DD];
__device__ float g_c;
__device__ __align__(16) float g_xt[NN * DD];     // x @ weight
__device__ float g_s1[NN];                        // leaky(c + x.v1)
__device__ float g_n2[NN];                        // x.v2
__device__ int   g_node_cnt[NN];
__device__ int   g_node_idx[NN * CAPN];
__device__ __align__(16) int g_edge_cnt[MM];
__device__ int   g_edge_idx[MM * CAPE];
__device__ __align__(16) float g_edge[MM * DD];
__device__ float g_e2[MM];

// ---------------- KZ0: zero edge counters + tiny precomputes ---------------------
__global__ void kz0(const float* __restrict__ W2, const float* __restrict__ W3,
                    const float* __restrict__ wc, const float* __restrict__ a,
                    const float* __restrict__ a2) {
    int b = blockIdx.x, t = threadIdx.x;
    if (b < 4) {
        int i = (b * 256 + t) * 4;
        *reinterpret_cast<int4*>(&g_edge_cnt[i]) = make_int4(0, 0, 0, 0);
        return;
    }
    if (t < FIN) {
        float s1 = 0.f, s2 = 0.f;
        #pragma unroll 4
        for (int c = 0; c < DD; c++) {
            float w = W2[t * DD + c];
            s1 += w * a[DD + c];
            s2 += w * a2[c];
        }
        g_v1[t] = s1; g_v2[t] = s2;
    }
    if (t < DD) {
        float s = 0.f;
        #pragma unroll 4
        for (int c = 0; c < DD; c++) s += W3[t * DD + c] * a2[DD + c];
        g_w3v[t] = s;
    }
    if (t == 0) {
        float s = 0.f;
        for (int c = 0; c < DD; c++) s += wc[c] * a[c];
        g_c = s;
    }
}

// ---------------- K-NOP: padding launch so k_scan is the 4th launch (ncu window) -
__global__ void knop() {}

// ---------------- K-GEMM: xt = x @ weight + fused s1/n2 --------------------------
__global__ void __launch_bounds__(128) k_gemm(const float* __restrict__ x,
                                              const float* __restrict__ W) {
    __shared__ float2 xs[FIN][9];
    int t = threadIdx.x;
    int r0 = blockIdx.x * 16;

    for (int i = t; i < 16 * FIN; i += 128) {
        int r = i >> 8;
        int k = i & (FIN - 1);
        float v = x[(r0 + r) * FIN + k];
        reinterpret_cast<float*>(&xs[k][r >> 1])[r & 1] = v;
    }
    __syncthreads();

    unsigned long long acc[8];
    #pragma unroll
    for (int p = 0; p < 8; p++) acc[p] = 0ull;

    const float* Wc = W + t;
    #pragma unroll 4
    for (int k = 0; k < FIN; k++) {
        float w = Wc[k * DD];
        unsigned wu = __float_as_uint(w);
        unsigned long long bb;
        asm("mov.b64 %0, {%1, %1};" : "=l"(bb) : "r"(wu));
        #pragma unroll
        for (int p = 0; p < 8; p++) {
            unsigned long long xp = *reinterpret_cast<const unsigned long long*>(&xs[k][p]);
            asm("fma.rn.f32x2 %0, %1, %2, %0;" : "+l"(acc[p]) : "l"(xp), "l"(bb));
        }
    }

    #pragma unroll
    for (int p = 0; p < 8; p++) {
        unsigned lo, hi;
        asm("mov.b64 {%0, %1}, %2;" : "=r"(lo), "=r"(hi) : "l"(acc[p]));
        g_xt[(r0 + 2 * p) * DD + t]     = __uint_as_float(lo);
        g_xt[(r0 + 2 * p + 1) * DD + t] = __uint_as_float(hi);
    }

    // fused s1/n2 for these 16 rows (x already in smem)
    {
        __shared__ float rb[2][4][16];
        int row = t & 15, seg = t >> 4;
        float p1 = 0.f, p2 = 0.f;
        #pragma unroll 4
        for (int kk = 0; kk < 32; kk++) {
            int k = seg * 32 + kk;
            float xv = reinterpret_cast<const float*>(&xs[k][row >> 1])[row & 1];
            p1 += xv * g_v1[k];
            p2 += xv * g_v2[k];
        }
        p1 += __shfl_xor_sync(0xffffffffu, p1, 16);
        p2 += __shfl_xor_sync(0xffffffffu, p2, 16);
        int warp = t >> 5, lane = t & 31;
        if (lane < 16) { rb[0][warp][lane] = p1; rb[1][warp][lane] = p2; }
        __syncthreads();
        if (t < 16) {
            float s = g_c + ((rb[0][0][t] + rb[0][1][t]) + (rb[0][2][t] + rb[0][3][t]));
            g_s1[r0 + t] = (s > 0.f) ? s : 0.2f * s;
            g_n2[r0 + t] = (rb[1][0][t] + rb[1][1][t]) + (rb[1][2][t] + rb[1][3][t]);
        }
    }
}

// ---------------- K-SCAN: warp-per-row, pipelined chunks, all-lane extraction ----
// 1024 blocks x 256 threads (8 warps = 8 rows). 8 chunks of 512 cols per row;
// chunk c+1's 4 LDG.128 are issued BEFORE extracting chunk c (loads always in flight).
__global__ void __launch_bounds__(256) k_scan(const float* __restrict__ adj) {
    int warp = threadIdx.x >> 5, lane = threadIdx.x & 31;
    int row = blockIdx.x * 8 + warp;
    const float4* r4 = reinterpret_cast<const float4*>(adj + (size_t)row * MM);
    int* nrow = g_node_idx + row * CAPN;
    int base = 0;

    float4 v[4];
    #pragma unroll
    for (int k = 0; k < 4; k++) v[k] = __ldcs(&r4[(k << 5) + lane]);

    #pragma unroll 1
    for (int c = 0; c < 8; c++) {
        float4 nv[4];
        if (c < 7) {
            const float4* p = r4 + ((c + 1) << 7);
            #pragma unroll
            for (int k = 0; k < 4; k++) nv[k] = __ldcs(&p[(k << 5) + lane]);
        }
        unsigned mask = 0;
        #pragma unroll
        for (int k = 0; k < 4; k++) {
            mask |= ((unsigned)(v[k].x > 0.f)        | ((unsigned)(v[k].y > 0.f) << 1)
                   | ((unsigned)(v[k].z > 0.f) << 2) | ((unsigned)(v[k].w > 0.f) << 3)) << (k << 2);
        }
        int cnt = __popc(mask);
        int pref = cnt;
        #pragma unroll
        for (int o = 1; o < 32; o <<= 1) {
            int n = __shfl_up_sync(0xffffffffu, pref, o);
            if (lane >= o) pref += n;
        }
        int total = __shfl_sync(0xffffffffu, pref, 31);
        int pos = base + pref - cnt;
        int cb = (c << 9) + (lane << 2);
        while (mask) {
            int b = __ffs(mask) - 1; mask &= mask - 1;
            int mcol = cb + ((b >> 2) << 7) + (b & 3);
            if (pos < CAPN) nrow[pos] = mcol;
            pos++;
            int slot = atomicAdd(&g_edge_cnt[mcol], 1);
            if (slot < CAPE) g_edge_idx[mcol * CAPE + slot] = row;
        }
        base += total;
        #pragma unroll
        for (int k = 0; k < 4; k++) v[k] = nv[k];
    }
    if (lane == 0) g_node_cnt[row] = base;
}

// ---------------- K3: block-per-edge; 4 warps split members ----------------------
__global__ void __launch_bounds__(128) k3() {
    __shared__ int   soff[CAPE];
    __shared__ float sw[CAPE];
    __shared__ float4 racc[4][32];
    __shared__ float rden[4];
    int t = threadIdx.x, warp = t >> 5, lane = t & 31;
    int m = blockIdx.x;
    int cnt = min(g_edge_cnt[m], CAPE);
    const int* el = g_edge_idx + m * CAPE;

    float den = 0.f;
    for (int k = t; k < cnt; k += 128) {
        int idx = el[k];
        float e = __expf(g_s1[idx]);     // scores bounded: max-free softmax safe
        soff[k] = idx * 32;
        sw[k] = e;
        den += e;
    }
    #pragma unroll
    for (int o = 16; o > 0; o >>= 1) den += __shfl_xor_sync(0xffffffffu, den, o);
    if (lane == 0) rden[warp] = den;
    __syncthreads();
    den = (rden[0] + rden[1]) + (rden[2] + rden[3]);
    float inv = (cnt > 0) ? __frcp_rn(den) : 0.f;

    const float4* xt4 = reinterpret_cast<const float4*>(g_xt);
    float4 A0 = make_float4(0.f, 0.f, 0.f, 0.f), A1 = A0, A2 = A0, A3 = A0;
    int i = warp;
    #pragma unroll 1
    for (; i + 12 < cnt; i += 16) {
        int o0 = soff[i], o1 = soff[i + 4], o2 = soff[i + 8], o3 = soff[i + 12];
        float w0 = sw[i], w1 = sw[i + 4], w2 = sw[i + 8], w3 = sw[i + 12];
        float4 p0 = xt4[o0 + lane], p1 = xt4[o1 + lane];
        float4 p2 = xt4[o2 + lane], p3 = xt4[o3 + lane];
        A0.x += w0 * p0.x; A0.y += w0 * p0.y; A0.z += w0 * p0.z; A0.w += w0 * p0.w;
        A1.x += w1 * p1.x; A1.y += w1 * p1.y; A1.z += w1 * p1.z; A1.w += w1 * p1.w;
        A2.x += w2 * p2.x; A2.y += w2 * p2.y; A2.z += w2 * p2.z; A2.w += w2 * p2.w;
        A3.x += w3 * p3.x; A3.y += w3 * p3.y; A3.z += w3 * p3.z; A3.w += w3 * p3.w;
    }
    #pragma unroll 1
    for (; i < cnt; i += 4) {
        float w0 = sw[i];
        float4 p0 = xt4[soff[i] + lane];
        A0.x += w0 * p0.x; A0.y += w0 * p0.y; A0.z += w0 * p0.z; A0.w += w0 * p0.w;
    }
    A0.x += (A1.x + A2.x) + A3.x; A0.y += (A1.y + A2.y) + A3.y;
    A0.z += (A1.z + A2.z) + A3.z; A0.w += (A1.w + A2.w) + A3.w;
    racc[warp][lane] = A0;
    __syncthreads();
    if (warp == 0) {
        float4 a0 = racc[0][lane], a1 = racc[1][lane], a2 = racc[2][lane], a3 = racc[3][lane];
        float4 r;
        r.x = ((a0.x + a1.x) + (a2.x + a3.x)) * inv;
        r.y = ((a0.y + a1.y) + (a2.y + a3.y)) * inv;
        r.z = ((a0.z + a1.z) + (a2.z + a3.z)) * inv;
        r.w = ((a0.w + a1.w) + (a2.w + a3.w)) * inv;
        reinterpret_cast<float4*>(g_edge)[m * 32 + lane] = r;
        float4 wv = reinterpret_cast<const float4*>(g_w3v)[lane];
        float part = r.x * wv.x + r.y * wv.y + r.z * wv.z + r.w * wv.w;
        #pragma unroll
        for (int o = 16; o > 0; o >>= 1) part += __shfl_xor_sync(0xffffffffu, part, o);
        if (lane == 0) g_e2[m] = part;
    }
}

// ---------------- K5: warp-per-node, register weights via shfl; ELU --------------
__global__ void __launch_bounds__(256) k5(float* __restrict__ out) {
    int t = threadIdx.x, lane = t & 31;
    int j = blockIdx.x * 8 + (t >> 5);
    int cnt = min(g_node_cnt[j], CAPN);
    const int* nl = g_node_idx + j * CAPN;
    float n2 = g_n2[j];

    int off0 = 0, off1 = 0;
    float e0 = 0.f, e1 = 0.f;
    if (lane < cnt) {
        int idx = nl[lane];
        off0 = idx * 32;
        float s = g_e2[idx] + n2;
        s = (s > 0.f) ? s : 0.2f * s;
        e0 = __expf(s);
    }
    if (32 + lane < cnt) {
        int idx = nl[32 + lane];
        off1 = idx * 32;
        float s = g_e2[idx] + n2;
        s = (s > 0.f) ? s : 0.2f * s;
        e1 = __expf(s);
    }
    float den = e0 + e1;
    #pragma unroll
    for (int o = 16; o > 0; o >>= 1) den += __shfl_xor_sync(0xffffffffu, den, o);
    float inv = (cnt > 0) ? __frcp_rn(den) : 0.f;

    const float4* ed4 = reinterpret_cast<const float4*>(g_edge);
    float4 A0 = make_float4(0.f, 0.f, 0.f, 0.f), A1 = A0, A2 = A0, A3 = A0;
    int c0 = min(cnt, 32);
    int i = 0;
    #pragma unroll 1
    for (; i + 4 <= c0; i += 4) {
        int   o0 = __shfl_sync(0xffffffffu, off0, i);
        int   o1 = __shfl_sync(0xffffffffu, off0, i + 1);
        int   o2 = __shfl_sync(0xffffffffu, off0, i + 2);
        int   o3 = __shfl_sync(0xffffffffu, off0, i + 3);
        float w0 = __shfl_sync(0xffffffffu, e0, i);
        float w1 = __shfl_sync(0xffffffffu, e0, i + 1);
        float w2 = __shfl_sync(0xffffffffu, e0, i + 2);
        float w3 = __shfl_sync(0xffffffffu, e0, i + 3);
        float4 p0 = ed4[o0 + lane], p1 = ed4[o1 + lane];
        float4 p2 = ed4[o2 + lane], p3 = ed4[o3 + lane];
        A0.x += w0 * p0.x; A0.y += w0 * p0.y; A0.z += w0 * p0.z; A0.w += w0 * p0.w;
        A1.x += w1 * p1.x; A1.y += w1 * p1.y; A1.z += w1 * p1.z; A1.w += w1 * p1.w;
        A2.x += w2 * p2.x; A2.y += w2 * p2.y; A2.z += w2 * p2.z; A2.w += w2 * p2.w;
        A3.x += w3 * p3.x; A3.y += w3 * p3.y; A3.z += w3 * p3.z; A3.w += w3 * p3.w;
    }
    #pragma unroll 1
    for (; i < c0; i++) {
        int   o0 = __shfl_sync(0xffffffffu, off0, i);
        float w0 = __shfl_sync(0xffffffffu, e0, i);
        float4 p0 = ed4[o0 + lane];
        A0.x += w0 * p0.x; A0.y += w0 * p0.y; A0.z += w0 * p0.z; A0.w += w0 * p0.w;
    }
    #pragma unroll 1
    for (i = 32; i < cnt; i++) {
        int   o0 = __shfl_sync(0xffffffffu, off1, i - 32);
        float w0 = __shfl_sync(0xffffffffu, e1, i - 32);
        float4 p0 = ed4[o0 + lane];
        A0.x += w0 * p0.x; A0.y += w0 * p0.y; A0.z += w0 * p0.z; A0.w += w0 * p0.w;
    }
    float4 r;
    r.x = ((A0.x + A1.x) + (A2.x + A3.x)) * inv;
    r.y = ((A0.y + A1.y) + (A2.y + A3.y)) * inv;
    r.z = ((A0.z + A1.z) + (A2.z + A3.z)) * inv;
    r.w = ((A0.w + A1.w) + (A2.w + A3.w)) * inv;
    r.x = (r.x > 0.f) ? r.x : (__expf(r.x) - 1.f);
    r.y = (r.y > 0.f) ? r.y : (__expf(r.y) - 1.f);
    r.z = (r.z > 0.f) ? r.z : (__expf(r.z) - 1.f);
    r.w = (r.w > 0.f) ? r.w : (__expf(r.w) - 1.f);
    reinterpret_cast<float4*>(out)[j * 32 + lane] = r;
}

// ---------------- launch ---------------------------------------------------------
extern "C" void kernel_launch(void* const* d_in, const int* in_sizes, int n_in,
                              void* d_out, int out_size) {
    const float* x   = (const float*)d_in[0];
    const float* adj = (const float*)d_in[1];
    const float* W   = (const float*)d_in[2];
    const float* W2  = (const float*)d_in[3];
    const float* W3  = (const float*)d_in[4];
    const float* wc  = (const float*)d_in[5];
    const float* a   = (const float*)d_in[6];
    const float* a2  = (const float*)d_in[7];
    float* out = (float*)d_out;

    kz0<<<5, 256>>>(W2, W3, wc, a, a2);       // launch 1
    k_gemm<<<NN / 16, 128>>>(x, W);           // launch 2
    knop<<<1, 32>>>();                        // launch 3 (ncu window pad)
    k_scan<<<NN / 8, 256>>>(adj);             // launch 4  <- ncu captures this
    k3<<<MM, 128>>>();                        // launch 5
    k5<<<NN / 8, 256>>>(out);                 // launch 6
}

// round 15
// speedup vs baseline: 1.0203x; 1.0203x over previous
#include <cuda_runtime.h>
#include <cstdint>
#include <math.h>

// Problem sizes
#define NN   8192
#define MM   4096
#define FIN  256
#define DD   128
#define CAPN 64
#define CAPE 128

// ---------------- device scratch ----------------
__device__ __align__(16) float g_v1[FIN];
__device__ __align__(16) float g_v2[FIN];
__device__ __align__(16) float g_w3v[DD];
__device__ float g_c;
__device__ __align__(16) float g_xt[NN * DD];     // x @ weight
__device__ float g_s1[NN];                        // leaky(c + x.v1)
__device__ float g_n2[NN];                        // x.v2
__device__ int   g_node_cnt[NN];
__device__ int   g_node_idx[NN * CAPN];
__device__ __align__(16) int g_edge_cnt[MM];
__device__ int   g_edge_idx[MM * CAPE];
__device__ __align__(16) float g_edge[MM * DD];
__device__ float g_e2[MM];

// ---------------- KZ0: zero edge counters + tiny precomputes ---------------------
__global__ void kz0(const float* __restrict__ W2, const float* __restrict__ W3,
                    const float* __restrict__ wc, const float* __restrict__ a,
                    const float* __restrict__ a2) {
    int b = blockIdx.x, t = threadIdx.x;
    if (b < 4) {
        int i = (b * 256 + t) * 4;
        *reinterpret_cast<int4*>(&g_edge_cnt[i]) = make_int4(0, 0, 0, 0);
        return;
    }
    if (t < FIN) {
        float s1 = 0.f, s2 = 0.f;
        #pragma unroll 4
        for (int c = 0; c < DD; c++) {
            float w = W2[t * DD + c];
            s1 += w * a[DD + c];
            s2 += w * a2[c];
        }
        g_v1[t] = s1; g_v2[t] = s2;
    }
    if (t < DD) {
        float s = 0.f;
        #pragma unroll 4
        for (int c = 0; c < DD; c++) s += W3[t * DD + c] * a2[DD + c];
        g_w3v[t] = s;
    }
    if (t == 0) {
        float s = 0.f;
        for (int c = 0; c < DD; c++) s += wc[c] * a[c];
        g_c = s;
    }
}

// ---------------- K-NOP: padding launch so k_gemm is the 4th launch (ncu window) -
__global__ void knop() {}

// ---------------- K-GEMM v2: 8 rows/block, LDS.128 x-reads, unroll 8 -------------
// 1024 blocks x 128 threads. xs row stride 48B (16B-aligned for ulonglong2 loads).
__global__ void __launch_bounds__(128) k_gemm(const float* __restrict__ x,
                                              const float* __restrict__ W) {
    __shared__ __align__(16) float2 xs[FIN][6];   // [k][p], p=0..3 used (8 rows), 48B stride
    int t = threadIdx.x;
    int r0 = blockIdx.x * 8;

    for (int i = t; i < 8 * FIN; i += 128) {
        int r = i >> 8;              // 0..7
        int k = i & (FIN - 1);       // 0..255
        float v = x[(r0 + r) * FIN + k];
        reinterpret_cast<float*>(&xs[k][r >> 1])[r & 1] = v;
    }
    __syncthreads();

    unsigned long long acc[4];
    #pragma unroll
    for (int p = 0; p < 4; p++) acc[p] = 0ull;

    const float* Wc = W + t;
    #pragma unroll 8
    for (int k = 0; k < FIN; k++) {
        float w = Wc[k * DD];
        unsigned wu = __float_as_uint(w);
        unsigned long long bb;
        asm("mov.b64 %0, {%1, %1};" : "=l"(bb) : "r"(wu));
        const ulonglong2* xk = reinterpret_cast<const ulonglong2*>(&xs[k][0]);
        ulonglong2 a01 = xk[0];      // rows 0-3 (2 x f32x2)
        ulonglong2 a23 = xk[1];      // rows 4-7
        asm("fma.rn.f32x2 %0, %1, %2, %0;" : "+l"(acc[0]) : "l"(a01.x), "l"(bb));
        asm("fma.rn.f32x2 %0, %1, %2, %0;" : "+l"(acc[1]) : "l"(a01.y), "l"(bb));
        asm("fma.rn.f32x2 %0, %1, %2, %0;" : "+l"(acc[2]) : "l"(a23.x), "l"(bb));
        asm("fma.rn.f32x2 %0, %1, %2, %0;" : "+l"(acc[3]) : "l"(a23.y), "l"(bb));
    }

    #pragma unroll
    for (int p = 0; p < 4; p++) {
        unsigned lo, hi;
        asm("mov.b64 {%0, %1}, %2;" : "=r"(lo), "=r"(hi) : "l"(acc[p]));
        g_xt[(r0 + 2 * p) * DD + t]     = __uint_as_float(lo);
        g_xt[(r0 + 2 * p + 1) * DD + t] = __uint_as_float(hi);
    }

    // fused s1/n2 for these 8 rows (x already in smem)
    {
        __shared__ float rb[2][4][8];
        int row = t & 7, seg = t >> 3;       // 16 segs x 16 k each
        float p1 = 0.f, p2 = 0.f;
        #pragma unroll 4
        for (int kk = 0; kk < 16; kk++) {
            int k = seg * 16 + kk;
            float xv = reinterpret_cast<const float*>(&xs[k][row >> 1])[row & 1];
            p1 += xv * g_v1[k];
            p2 += xv * g_v2[k];
        }
        // lanes with same row differ in t bits 3,4 within the warp
        p1 += __shfl_xor_sync(0xffffffffu, p1, 8);
        p1 += __shfl_xor_sync(0xffffffffu, p1, 16);
        p2 += __shfl_xor_sync(0xffffffffu, p2, 8);
        p2 += __shfl_xor_sync(0xffffffffu, p2, 16);
        int warp = t >> 5, lane = t & 31;
        if (lane < 8) { rb[0][warp][lane] = p1; rb[1][warp][lane] = p2; }
        __syncthreads();
        if (t < 8) {
            float s = g_c + ((rb[0][0][t] + rb[0][1][t]) + (rb[0][2][t] + rb[0][3][t]));
            g_s1[r0 + t] = (s > 0.f) ? s : 0.2f * s;
            g_n2[r0 + t] = (rb[1][0][t] + rb[1][1][t]) + (rb[1][2][t] + rb[1][3][t]);
        }
    }
}

// ---------------- K-SCAN: warp-per-row, pipelined chunks, all-lane extraction ----
__global__ void __launch_bounds__(256) k_scan(const float* __restrict__ adj) {
    int warp = threadIdx.x >> 5, lane = threadIdx.x & 31;
    int row = blockIdx.x * 8 + warp;
    const float4* r4 = reinterpret_cast<const float4*>(adj + (size_t)row * MM);
    int* nrow = g_node_idx + row * CAPN;
    int base = 0;

    float4 v[4];
    #pragma unroll
    for (int k = 0; k < 4; k++) v[k] = __ldcs(&r4[(k << 5) + lane]);

    #pragma unroll 1
    for (int c = 0; c < 8; c++) {
        float4 nv[4];
        if (c < 7) {
            const float4* p = r4 + ((c + 1) << 7);
            #pragma unroll
            for (int k = 0; k < 4; k++) nv[k] = __ldcs(&p[(k << 5) + lane]);
        }
        unsigned mask = 0;
        #pragma unroll
        for (int k = 0; k < 4; k++) {
            mask |= ((unsigned)(v[k].x > 0.f)        | ((unsigned)(v[k].y > 0.f) << 1)
                   | ((unsigned)(v[k].z > 0.f) << 2) | ((unsigned)(v[k].w > 0.f) << 3)) << (k << 2);
        }
        int cnt = __popc(mask);
        int pref = cnt;
        #pragma unroll
        for (int o = 1; o < 32; o <<= 1) {
            int n = __shfl_up_sync(0xffffffffu, pref, o);
            if (lane >= o) pref += n;
        }
        int total = __shfl_sync(0xffffffffu, pref, 31);
        int pos = base + pref - cnt;
        int cb = (c << 9) + (lane << 2);
        while (mask) {
            int b = __ffs(mask) - 1; mask &= mask - 1;
            int mcol = cb + ((b >> 2) << 7) + (b & 3);
            if (pos < CAPN) nrow[pos] = mcol;
            pos++;
            int slot = atomicAdd(&g_edge_cnt[mcol], 1);
            if (slot < CAPE) g_edge_idx[mcol * CAPE + slot] = row;
        }
        base += total;
        #pragma unroll
        for (int k = 0; k < 4; k++) v[k] = nv[k];
    }
    if (lane == 0) g_node_cnt[row] = base;
}

// ---------------- K3: block-per-edge; 4 warps split members ----------------------
__global__ void __launch_bounds__(128) k3() {
    __shared__ int   soff[CAPE];
    __shared__ float sw[CAPE];
    __shared__ float4 racc[4][32];
    __shared__ float rden[4];
    int t = threadIdx.x, warp = t >> 5, lane = t & 31;
    int m = blockIdx.x;
    int cnt = min(g_edge_cnt[m], CAPE);
    const int* el = g_edge_idx + m * CAPE;

    float den = 0.f;
    for (int k = t; k < cnt; k += 128) {
        int idx = el[k];
        float e = __expf(g_s1[idx]);     // scores bounded: max-free softmax safe
        soff[k] = idx * 32;
        sw[k] = e;
        den += e;
    }
    #pragma unroll
    for (int o = 16; o > 0; o >>= 1) den += __shfl_xor_sync(0xffffffffu, den, o);
    if (lane == 0) rden[warp] = den;
    __syncthreads();
    den = (rden[0] + rden[1]) + (rden[2] + rden[3]);
    float inv = (cnt > 0) ? __frcp_rn(den) : 0.f;

    const float4* xt4 = reinterpret_cast<const float4*>(g_xt);
    float4 A0 = make_float4(0.f, 0.f, 0.f, 0.f), A1 = A0, A2 = A0, A3 = A0;
    int i = warp;
    #pragma unroll 1
    for (; i + 12 < cnt; i += 16) {
        int o0 = soff[i], o1 = soff[i + 4], o2 = soff[i + 8], o3 = soff[i + 12];
        float w0 = sw[i], w1 = sw[i + 4], w2 = sw[i + 8], w3 = sw[i + 12];
        float4 p0 = xt4[o0 + lane], p1 = xt4[o1 + lane];
        float4 p2 = xt4[o2 + lane], p3 = xt4[o3 + lane];
        A0.x += w0 * p0.x; A0.y += w0 * p0.y; A0.z += w0 * p0.z; A0.w += w0 * p0.w;
        A1.x += w1 * p1.x; A1.y += w1 * p1.y; A1.z += w1 * p1.z; A1.w += w1 * p1.w;
        A2.x += w2 * p2.x; A2.y += w2 * p2.y; A2.z += w2 * p2.z; A2.w += w2 * p2.w;
        A3.x += w3 * p3.x; A3.y += w3 * p3.y; A3.z += w3 * p3.z; A3.w += w3 * p3.w;
    }
    #pragma unroll 1
    for (; i < cnt; i += 4) {
        float w0 = sw[i];
        float4 p0 = xt4[soff[i] + lane];
        A0.x += w0 * p0.x; A0.y += w0 * p0.y; A0.z += w0 * p0.z; A0.w += w0 * p0.w;
    }
    A0.x += (A1.x + A2.x) + A3.x; A0.y += (A1.y + A2.y) + A3.y;
    A0.z += (A1.z + A2.z) + A3.z; A0.w += (A1.w + A2.w) + A3.w;
    racc[warp][lane] = A0;
    __syncthreads();
    if (warp == 0) {
        float4 a0 = racc[0][lane], a1 = racc[1][lane], a2 = racc[2][lane], a3 = racc[3][lane];
        float4 r;
        r.x = ((a0.x + a1.x) + (a2.x + a3.x)) * inv;
        r.y = ((a0.y + a1.y) + (a2.y + a3.y)) * inv;
        r.z = ((a0.z + a1.z) + (a2.z + a3.z)) * inv;
        r.w = ((a0.w + a1.w) + (a2.w + a3.w)) * inv;
        reinterpret_cast<float4*>(g_edge)[m * 32 + lane] = r;
        float4 wv = reinterpret_cast<const float4*>(g_w3v)[lane];
        float part = r.x * wv.x + r.y * wv.y + r.z * wv.z + r.w * wv.w;
        #pragma unroll
        for (int o = 16; o > 0; o >>= 1) part += __shfl_xor_sync(0xffffffffu, part, o);
        if (lane == 0) g_e2[m] = part;
    }
}

// ---------------- K5: warp-per-node, register weights via shfl; ELU --------------
__global__ void __launch_bounds__(256) k5(float* __restrict__ out) {
    int t = threadIdx.x, lane = t & 31;
    int j = blockIdx.x * 8 + (t >> 5);
    int cnt = min(g_node_cnt[j], CAPN);
    const int* nl = g_node_idx + j * CAPN;
    float n2 = g_n2[j];

    int off0 = 0, off1 = 0;
    float e0 = 0.f, e1 = 0.f;
    if (lane < cnt) {
        int idx = nl[lane];
        off0 = idx * 32;
        float s = g_e2[idx] + n2;
        s = (s > 0.f) ? s : 0.2f * s;
        e0 = __expf(s);
    }
    if (32 + lane < cnt) {
        int idx = nl[32 + lane];
        off1 = idx * 32;
        float s = g_e2[idx] + n2;
        s = (s > 0.f) ? s : 0.2f * s;
        e1 = __expf(s);
    }
    float den = e0 + e1;
    #pragma unroll
    for (int o = 16; o > 0; o >>= 1) den += __shfl_xor_sync(0xffffffffu, den, o);
    float inv = (cnt > 0) ? __frcp_rn(den) : 0.f;

    const float4* ed4 = reinterpret_cast<const float4*>(g_edge);
    float4 A0 = make_float4(0.f, 0.f, 0.f, 0.f), A1 = A0, A2 = A0, A3 = A0;
    int c0 = min(cnt, 32);
    int i = 0;
    #pragma unroll 1
    for (; i + 4 <= c0; i += 4) {
        int   o0 = __shfl_sync(0xffffffffu, off0, i);
        int   o1 = __shfl_sync(0xffffffffu, off0, i + 1);
        int   o2 = __shfl_sync(0xffffffffu, off0, i + 2);
        int   o3 = __shfl_sync(0xffffffffu, off0, i + 3);
        float w0 = __shfl_sync(0xffffffffu, e0, i);
        float w1 = __shfl_sync(0xffffffffu, e0, i + 1);
        float w2 = __shfl_sync(0xffffffffu, e0, i + 2);
        float w3 = __shfl_sync(0xffffffffu, e0, i + 3);
        float4 p0 = ed4[o0 + lane], p1 = ed4[o1 + lane];
        float4 p2 = ed4[o2 + lane], p3 = ed4[o3 + lane];
        A0.x += w0 * p0.x; A0.y += w0 * p0.y; A0.z += w0 * p0.z; A0.w += w0 * p0.w;
        A1.x += w1 * p1.x; A1.y += w1 * p1.y; A1.z += w1 * p1.z; A1.w += w1 * p1.w;
        A2.x += w2 * p2.x; A2.y += w2 * p2.y; A2.z += w2 * p2.z; A2.w += w2 * p2.w;
        A3.x += w3 * p3.x; A3.y += w3 * p3.y; A3.z += w3 * p3.z; A3.w += w3 * p3.w;
    }
    #pragma unroll 1
    for (; i < c0; i++) {
        int   o0 = __shfl_sync(0xffffffffu, off0, i);
        float w0 = __shfl_sync(0xffffffffu, e0, i);
        float4 p0 = ed4[o0 + lane];
        A0.x += w0 * p0.x; A0.y += w0 * p0.y; A0.z += w0 * p0.z; A0.w += w0 * p0.w;
    }
    #pragma unroll 1
    for (i = 32; i < cnt; i++) {
        int   o0 = __shfl_sync(0xffffffffu, off1, i - 32);
        float w0 = __shfl_sync(0xffffffffu, e1, i - 32);
        float4 p0 = ed4[o0 + lane];
        A0.x += w0 * p0.x; A0.y += w0 * p0.y; A0.z += w0 * p0.z; A0.w += w0 * p0.w;
    }
    float4 r;
    r.x = ((A0.x + A1.x) + (A2.x + A3.x)) * inv;
    r.y = ((A0.y + A1.y) + (A2.y + A3.y)) * inv;
    r.z = ((A0.z + A1.z) + (A2.z + A3.z)) * inv;
    r.w = ((A0.w + A1.w) + (A2.w + A3.w)) * inv;
    r.x = (r.x > 0.f) ? r.x : (__expf(r.x) - 1.f);
    r.y = (r.y > 0.f) ? r.y : (__expf(r.y) - 1.f);
    r.z = (r.z > 0.f) ? r.z : (__expf(r.z) - 1.f);
    r.w = (r.w > 0.f) ? r.w : (__expf(r.w) - 1.f);
    reinterpret_cast<float4*>(out)[j * 32 + lane] = r;
}

// ---------------- launch ---------------------------------------------------------
extern "C" void kernel_launch(void* const* d_in, const int* in_sizes, int n_in,
                              void* d_out, int out_size) {
    const float* x   = (const float*)d_in[0];
    const float* adj = (const float*)d_in[1];
    const float* W   = (const float*)d_in[2];
    const float* W2  = (const float*)d_in[3];
    const float* W3  = (const float*)d_in[4];
    const float* wc  = (const float*)d_in[5];
    const float* a   = (const float*)d_in[6];
    const float* a2  = (const float*)d_in[7];
    float* out = (float*)d_out;

    kz0<<<5, 256>>>(W2, W3, wc, a, a2);       // launch 1
    knop<<<1, 32>>>();                        // launch 2 (ncu window pad)
    k_scan<<<NN / 8, 256>>>(adj);             // launch 3
    k_gemm<<<NN / 8, 128>>>(x, W);            // launch 4  <- ncu captures this
    k3<<<MM, 128>>>();                        // launch 5
    k5<<<NN / 8, 256>>>(out);                 // launch 6
}